// round 13
// baseline (speedup 1.0000x reference)
#include <cuda_runtime.h>
#include <math.h>

// ---------------------------------------------------------------------------
// LinearDescent: linear attention with per-(b,h) 64x64 state reassociation.
// B=2, S=2048, H=1024, nh=16, hd=64, kg=8, din=128, P=2112, NPF=64.
// Round 13: kv+mpart fused (kvm): k/v live only in smem; MT accumulated via
// tf32 mma + atomicAdd per 8-token block. wprep folded into k1 grid.
// 3 kernels total. g_k/g_v eliminated (64MB traffic removed).
// ---------------------------------------------------------------------------

#define TOK_TOTAL 4096
#define S_LEN     2048
#define H_DIM     1024
#define NH        16
#define P_DIM     2112
#define NPF       64
#define DIN       128

typedef unsigned long long u64;
typedef unsigned int u32;

__device__ __forceinline__ u64 pack2b(float v) {
    u64 r; asm("mov.b64 %0, {%1,%1};" : "=l"(r) : "f"(v)); return r;
}
__device__ __forceinline__ u64 ffma2(u64 a, u64 b, u64 c) {
    u64 d; asm("fma.rn.f32x2 %0, %1, %2, %3;" : "=l"(d) : "l"(a), "l"(b), "l"(c)); return d;
}
__device__ __forceinline__ float2 unpk(u64 v) {
    float2 f; asm("mov.b64 {%0,%1}, %2;" : "=f"(f.x), "=f"(f.y) : "l"(v)); return f;
}
__device__ __forceinline__ void mma_tf32(float* c, u32 a0, u32 a1, u32 a2, u32 a3,
                                         u32 b0, u32 b1) {
    asm volatile("mma.sync.aligned.m16n8k8.row.col.f32.tf32.tf32.f32 "
                 "{%0,%1,%2,%3}, {%4,%5,%6,%7}, {%8,%9}, {%0,%1,%2,%3};"
                 : "+f"(c[0]), "+f"(c[1]), "+f"(c[2]), "+f"(c[3])
                 : "r"(a0), "r"(a1), "r"(a2), "r"(a3), "r"(b0), "r"(b1));
}

// scratch (device globals; allocation-free kernel_launch)
__device__ float g_k1[TOK_TOTAL * H_DIM];
__device__ float g_Mall[32 * 4096];   // per-(b,h) MT[e][d] (atomic accum)
__device__ float g_M0  [32 * 4096];   // prefix contribution (atomic accum)
__device__ float g_WqT [16384];       // [g][h][d]
__device__ float g_WvT [16384];
__device__ float g_WcT [16384];
__device__ float g_WkhT[8192];        // [h8][g][dd]

__device__ __forceinline__ int pos_idx(int s) { return (s < NPF) ? (S_LEN + s) : s; }

// ---------------------------------------------------------------------------
// K1: grouped conv via tf32 mma (grid (64, 9); y==8 blocks do weight
// transposes, y<8 do the GEMM). Also zeroes g_Mall / g_M0.
// smem: Xs 64x132, Ws 128x136. 103424 B, 2 CTA/SM.
// ---------------------------------------------------------------------------
extern "C" __global__ void __launch_bounds__(256, 2)
k1_kernel(const float* __restrict__ hidden, const float* __restrict__ Wkg,
          const float* __restrict__ Wq, const float* __restrict__ Wv,
          const float* __restrict__ Wc, const float* __restrict__ Wkh) {
    extern __shared__ float sm[];
    const int tid = threadIdx.x;
    const int g   = blockIdx.y;

    if (g == 8) {                     // ---- wprep duty ----
        const int bid = blockIdx.x;
        if (bid >= 4) return;
        float* sw = sm;
        if (bid < 3) {
            const float* src = (bid == 0) ? Wq : (bid == 1) ? Wv : Wc;
            float*       dst = (bid == 0) ? g_WqT : (bid == 1) ? g_WvT : g_WcT;
            for (int i = tid; i < 4096; i += 256) ((float4*)sw)[i] = ((const float4*)src)[i];
            __syncthreads();
            for (int j = tid; j < 16384; j += 256) {
                int gg = j >> 10, rem = j & 1023, h = rem >> 6, d = rem & 63;
                dst[j] = sw[d * 256 + h * 16 + gg];
            }
        } else {
            for (int i = tid; i < 2048; i += 256) ((float4*)sw)[i] = ((const float4*)Wkh)[i];
            __syncthreads();
            for (int j = tid; j < 8192; j += 256) {
                int h8 = j >> 10, rem = j & 1023, gg = rem >> 7, dd = rem & 127;
                g_WkhT[j] = sw[dd * 64 + gg * 8 + h8];
            }
        }
        return;
    }

    float* Xs = sm;              // 64*132 = 8448
    float* Ws = sm + 8448;       // 128*136 = 17408
    const int t0 = blockIdx.x * 64;

    if (blockIdx.x < 32) {
        float4 z = make_float4(0.f, 0.f, 0.f, 0.f);
        if (g == 0) {
            float4* p = (float4*)(g_Mall + (size_t)blockIdx.x * 4096);
#pragma unroll
            for (int i = 0; i < 4; i++) p[tid + i * 256] = z;
        } else if (g == 1) {
            float4* p = (float4*)(g_M0 + (size_t)blockIdx.x * 4096);
#pragma unroll
            for (int i = 0; i < 4; i++) p[tid + i * 256] = z;
        }
    }

#pragma unroll
    for (int i = 0; i < 8; i++) {
        int j = tid + i * 256;
        int row = j >> 5, c4 = (j & 31) * 4;
        *(float4*)&Xs[row * 132 + c4] =
            *(const float4*)(hidden + (size_t)(t0 + row) * H_DIM + g * DIN + c4);
    }
#pragma unroll
    for (int i = 0; i < 16; i++) {
        int j = tid + i * 256;
        int row = j >> 5, c4 = (j & 31) * 4;
        *(float4*)&Ws[row * 136 + c4] =
            *(const float4*)(Wkg + (size_t)g * 16384 + row * 128 + c4);
    }
    __syncthreads();

    const int lane = tid & 31, wid = tid >> 5;
    const int gID = lane >> 2, tID = lane & 3;
    const int mt = wid & 3;
    const int nh = wid >> 2;
    float acc[8][4];
#pragma unroll
    for (int n = 0; n < 8; n++)
#pragma unroll
        for (int j = 0; j < 4; j++) acc[n][j] = 0.f;

    const float* Ar0 = Xs + (mt * 16 + gID) * 132;
    const float* Ar1 = Ar0 + 8 * 132;
    const float* Bbase = Ws + nh * 64 + gID;
#pragma unroll
    for (int k0 = 0; k0 < 128; k0 += 8) {
        u32 a0 = __float_as_uint(Ar0[k0 + tID]);
        u32 a1 = __float_as_uint(Ar1[k0 + tID]);
        u32 a2 = __float_as_uint(Ar0[k0 + tID + 4]);
        u32 a3 = __float_as_uint(Ar1[k0 + tID + 4]);
        const float* B0 = Bbase + (k0 + tID) * 136;
        const float* B1 = B0 + 4 * 136;
#pragma unroll
        for (int n = 0; n < 8; n++) {
            u32 b0 = __float_as_uint(B0[n * 8]);
            u32 b1 = __float_as_uint(B1[n * 8]);
            mma_tf32(acc[n], a0, a1, a2, a3, b0, b1);
        }
    }

    float* o0 = g_k1 + (size_t)(t0 + mt * 16 + gID) * H_DIM + g * DIN + nh * 64;
    float* o1 = o0 + 8 * H_DIM;
#pragma unroll
    for (int n = 0; n < 8; n++) {
        int col = n * 8 + tID * 2;
        *(float2*)&o0[col] = make_float2(acc[n][0], acc[n][1]);
        *(float2*)&o1[col] = make_float2(acc[n][2], acc[n][3]);
    }
}

// ---------------------------------------------------------------------------
// K2 (kvm): k and v projections into smem (stride-1032 tiles), then
// MT[e][d] += v^T k via tf32 mma + atomicAdd. 8 tokens/block, 512 blocks,
// 256 thr, 102912 B smem, 2 CTA/SM.
// smem floats: xs [0,8192) | ps [8192,9216) | vsm [9216,17472) stride 1032 |
//              ksm [17472,25728) stride 1032.
// ---------------------------------------------------------------------------
extern "C" __global__ void __launch_bounds__(256, 2)
kvm_kernel(const float* __restrict__ hidden,
           const float* __restrict__ p_attn,
           const float* __restrict__ p_expand) {
    extern __shared__ float sm[];
    float* xs  = sm;            // 8*1024
    float* ps  = sm + 8192;     // 8*128
    float* vsm = sm + 9216;     // 8*1032
    float* ksm = sm + 17472;    // 8*1032
    const int tid  = threadIdx.x;
    const int tok0 = blockIdx.x * 8;
    const int b    = tok0 / S_LEN;
    const int s0   = tok0 & (S_LEN - 1);
    const bool prefix = (s0 < NPF);

    {   // stage hidden (2048 float4)
        const float4* src = (const float4*)(hidden + (size_t)tok0 * H_DIM);
        float4* dst = (float4*)xs;
#pragma unroll
        for (int i = 0; i < 8; i++) dst[tid + i * 256] = src[tid + i * 256];
    }
#pragma unroll
    for (int i = 0; i < 4; i++) {   // ps: 1024 entries (p_attn rows 64..191)
        int e = tid + i * 256;
        int t = e >> 7, c = e & 127;
        int s = (tok0 + t) & (S_LEN - 1);
        ps[e] = p_attn[(size_t)(64 + c) * P_DIM + pos_idx(s)];
    }
    __syncthreads();

    // ---- V -> vsm ----
    {
        const int d0 = (tid & 31) * 2;
        const int g  = (tid >> 5) * 2;
        const u64* wv0 = (const u64*)(g_WvT + g * 1024 + d0);
        const u64* wv1 = (const u64*)(g_WvT + (g + 1) * 1024 + d0);
        const u64 pe0 = pack2b(p_expand[32 + g]);
        const u64 pe1 = pack2b(p_expand[33 + g]);
        u64 acc[2][8];
#pragma unroll
        for (int t = 0; t < 8; t++) { acc[0][t] = 0ull; acc[1][t] = 0ull; }
#pragma unroll
        for (int h = 0; h < NH; h++) {
            u64 w0 = wv0[h * 32], w1 = wv1[h * 32];
#pragma unroll
            for (int t = 0; t < 8; t++) {
                u64 x = *(const u64*)&xs[t * 1024 + h * 64 + d0];
                acc[0][t] = ffma2(x, w0, acc[0][t]);
                acc[1][t] = ffma2(x, w1, acc[1][t]);
            }
        }
#pragma unroll
        for (int t = 0; t < 8; t++) {
            u64 pv = *(const u64*)&ps[t * 128 + 64 + d0];
            *(u64*)&vsm[t * 1032 + g * 64 + d0]       = ffma2(pe0, pv, acc[0][t]);
            *(u64*)&vsm[t * 1032 + (g + 1) * 64 + d0] = ffma2(pe1, pv, acc[1][t]);
        }
    }
    // ---- K -> ksm ----
    __syncthreads();
    {
        const float4* src = (const float4*)(g_k1 + (size_t)tok0 * H_DIM);
        float4* dst = (float4*)xs;
#pragma unroll
        for (int i = 0; i < 8; i++) dst[tid + i * 256] = src[tid + i * 256];
    }
    __syncthreads();
    {
        const int dd0 = (tid & 63) * 2;
        const int h8  = (tid >> 6) * 2;
        const u64* wk0 = (const u64*)(g_WkhT + h8 * 1024 + dd0);
        const u64* wk1 = (const u64*)(g_WkhT + (h8 + 1) * 1024 + dd0);
        const int jj0 = h8 * 128 + dd0;
        const int jj1 = (h8 + 1) * 128 + dd0;
        const u64 pe0 = pack2b(p_expand[16 + (jj0 >> 6)]);
        const u64 pe1 = pack2b(p_expand[16 + (jj1 >> 6)]);
        const int d64 = dd0 & 63;
        u64 acc[2][8];
#pragma unroll
        for (int t = 0; t < 8; t++) { acc[0][t] = 0ull; acc[1][t] = 0ull; }
#pragma unroll
        for (int g = 0; g < 8; g++) {
            u64 w0 = wk0[g * 64], w1 = wk1[g * 64];
#pragma unroll
            for (int t = 0; t < 8; t++) {
                u64 x = *(const u64*)&xs[t * 1024 + g * 128 + dd0];
                acc[0][t] = ffma2(x, w0, acc[0][t]);
                acc[1][t] = ffma2(x, w1, acc[1][t]);
            }
        }
#pragma unroll
        for (int t = 0; t < 8; t++) {
            u64 pk = *(const u64*)&ps[t * 128 + d64];
            *(u64*)&ksm[t * 1032 + jj0] = ffma2(pe0, pk, acc[0][t]);
            *(u64*)&ksm[t * 1032 + jj1] = ffma2(pe1, pk, acc[1][t]);
        }
    }
    __syncthreads();

    // ---- MT accumulation: 64 tasks (16 heads x 4 e-tiles), 8 per warp ----
    const int wid = tid >> 5, lane = tid & 31;
    const int gID = lane >> 2, tID = lane & 3;
    float* Mall = g_Mall + (size_t)(b * 16) * 4096;
    float* M0p  = g_M0   + (size_t)(b * 16) * 4096;
#pragma unroll
    for (int rep = 0; rep < 8; rep++) {
        const int task = wid * 8 + rep;
        const int head = task >> 2;
        const int e0   = (task & 3) * 16;
        const float* vb = vsm + head * 64;
        const float* kb = ksm + head * 64;
        u32 a0 = __float_as_uint(vb[tID * 1032 + e0 + gID]);
        u32 a1 = __float_as_uint(vb[tID * 1032 + e0 + gID + 8]);
        u32 a2 = __float_as_uint(vb[(tID + 4) * 1032 + e0 + gID]);
        u32 a3 = __float_as_uint(vb[(tID + 4) * 1032 + e0 + gID + 8]);
        float acc[8][4];
#pragma unroll
        for (int n = 0; n < 8; n++)
#pragma unroll
            for (int j = 0; j < 4; j++) acc[n][j] = 0.f;
#pragma unroll
        for (int n = 0; n < 8; n++) {
            u32 b0 = __float_as_uint(kb[tID * 1032 + n * 8 + gID]);
            u32 b1 = __float_as_uint(kb[(tID + 4) * 1032 + n * 8 + gID]);
            mma_tf32(acc[n], a0, a1, a2, a3, b0, b1);
        }
        float* op = Mall + head * 4096;
        const int r0 = (e0 + gID) * 64 + tID * 2;
        const int r1 = (e0 + gID + 8) * 64 + tID * 2;
#pragma unroll
        for (int n = 0; n < 8; n++) {
            atomicAdd(&op[r0 + n * 8],     acc[n][0]);
            atomicAdd(&op[r0 + n * 8 + 1], acc[n][1]);
            atomicAdd(&op[r1 + n * 8],     acc[n][2]);
            atomicAdd(&op[r1 + n * 8 + 1], acc[n][3]);
        }
        if (prefix) {
            float* o0 = M0p + head * 4096;
#pragma unroll
            for (int n = 0; n < 8; n++) {
                atomicAdd(&o0[r0 + n * 8],     acc[n][0]);
                atomicAdd(&o0[r0 + n * 8 + 1], acc[n][1]);
                atomicAdd(&o0[r1 + n * 8],     acc[n][2]);
                atomicAdd(&o0[r1 + n * 8 + 1], acc[n][3]);
            }
        }
    }
}

// ---------------------------------------------------------------------------
// K3 (ctx): Q proj (d-pair), ctx = q @ M via tf32 mma, Wc (d-pair), gates,
// blend. 16 tok/block, 512 thr, 225.4KB smem, 1 CTA/SM. (Unchanged from R12.)
// ---------------------------------------------------------------------------
extern "C" __global__ void __launch_bounds__(512, 1)
ctx_out_kernel(const float* __restrict__ hidden,
               const float* __restrict__ p_attn,
               const float* __restrict__ p_expand,
               const float* __restrict__ Wg,
               const float* __restrict__ Ug,
               const float* __restrict__ Vg,
               const float* __restrict__ bg,
               float* __restrict__ out) {
    extern __shared__ float sm[];
    float* X    = sm;
    float* qp   = sm + 16384;
    float* Mb   = sm + 35840;
    float* Mout = sm + 35840;
    float* psq  = sm + 55296;
    float* gs   = sm + 56320;
    const int tid  = threadIdx.x;
    const int tok0 = blockIdx.x * 16;
    const int b    = tok0 / S_LEN;
    const int s0   = tok0 & (S_LEN - 1);
    const bool prefix = (s0 < NPF);

    {
        const float4* src = (const float4*)(hidden + (size_t)tok0 * H_DIM);
        float4* dst = (float4*)X;
#pragma unroll
        for (int i = 0; i < 8; i++) dst[tid + i * 512] = src[tid + i * 512];
    }
#pragma unroll
    for (int i = 0; i < 2; i++) {
        int e = tid + i * 512;
        int t = e >> 6, d = e & 63;
        int s = (tok0 + t) & (S_LEN - 1);
        psq[e] = p_attn[(size_t)d * P_DIM + pos_idx(s)];
    }
    __syncthreads();

    // ---- Q -> qp (padded stride 76) ----
    {
        const int d0 = (tid & 31) * 2;
        const int g  = tid >> 5;
        const u64* wq = (const u64*)(g_WqT + g * 1024 + d0);
        u64 acc[16];
#pragma unroll
        for (int t = 0; t < 16; t++) acc[t] = 0ull;
#pragma unroll
        for (int h = 0; h < NH; h++) {
            u64 w = wq[h * 32];
#pragma unroll
            for (int t = 0; t < 16; t++)
                acc[t] = ffma2(*(const u64*)&X[t * 1024 + h * 64 + d0], w, acc[t]);
        }
        const u64 pe2 = pack2b(p_expand[g]);
        float* row = qp + g * 1216 + d0;
#pragma unroll
        for (int t = 0; t < 16; t++) {
            u64 pq = *(const u64*)&psq[t * 64 + d0];
            *(u64*)&row[t * 76] = ffma2(pe2, pq, acc[t]);
        }
    }

    // ---- ctx = q @ M via mma : 4 stages x 4 heads ----
    const int wid  = tid >> 5;
    const int lane = tid & 31;
    const int gID  = lane >> 2, tID = lane & 3;
    const int hh   = wid >> 2;
    const int nq   = wid & 3;
    const float* Ma = g_Mall + (size_t)(b * 16) * 4096;
    const float* M0 = g_M0   + (size_t)(b * 16) * 4096;

    for (int stg = 0; stg < 4; stg++) {
        __syncthreads();
        {
            const u64* msrc = (const u64*)(Ma + (size_t)stg * 16384);
            const u64* zsrc = (const u64*)(M0 + (size_t)stg * 16384);
#pragma unroll
            for (int i = 0; i < 16; i++) {
                int j = tid + i * 512;
                int h2 = j >> 11, e = (j >> 5) & 63, dp = (j & 31) * 2;
                float* dst = Mb + h2 * 4864 + e * 76 + dp;
                if (prefix) {
                    float2 A = unpk(msrc[j]), Z = unpk(zsrc[j]);
                    dst[0] = A.x - Z.x; dst[1] = A.y - Z.y;
                } else {
                    *(u64*)dst = msrc[j];
                }
            }
        }
        __syncthreads();

        const int head = stg * 4 + hh;
        const float* qb = qp + head * 1216;
        const float* mb = Mb + hh * 4864;
        float acc[2][4];
#pragma unroll
        for (int j = 0; j < 2; j++)
#pragma unroll
            for (int i = 0; i < 4; i++) acc[j][i] = 0.f;
#pragma unroll
        for (int ks8 = 0; ks8 < 8; ks8++) {
            const int k0 = ks8 * 8;
            u32 a0 = __float_as_uint(qb[gID * 76 + k0 + tID]);
            u32 a1 = __float_as_uint(qb[(gID + 8) * 76 + k0 + tID]);
            u32 a2 = __float_as_uint(qb[gID * 76 + k0 + tID + 4]);
            u32 a3 = __float_as_uint(qb[(gID + 8) * 76 + k0 + tID + 4]);
#pragma unroll
            for (int j = 0; j < 2; j++) {
                int nt = nq * 2 + j;
                u32 b0 = __float_as_uint(mb[(nt * 8 + gID) * 76 + k0 + tID]);
                u32 b1 = __float_as_uint(mb[(nt * 8 + gID) * 76 + k0 + tID + 4]);
                mma_tf32(acc[j], a0, a1, a2, a3, b0, b1);
            }
        }
#pragma unroll
        for (int j = 0; j < 2; j++) {
            int col = head * 64 + (nq * 2 + j) * 8 + 2 * tID;
            *(float2*)&X[gID * 1024 + col]       = make_float2(acc[j][0], acc[j][1]);
            *(float2*)&X[(gID + 8) * 1024 + col] = make_float2(acc[j][2], acc[j][3]);
        }
    }
    __syncthreads();

    // ---- out = Wc head-mix (d-pair) ----
    {
        const int d0 = (tid & 31) * 2;
        const int g  = tid >> 5;
        const u64* wc = (const u64*)(g_WcT + g * 1024 + d0);
        u64 acc[16];
#pragma unroll
        for (int t = 0; t < 16; t++) acc[t] = 0ull;
#pragma unroll
        for (int h = 0; h < NH; h++) {
            u64 w = wc[h * 32];
#pragma unroll
            for (int t = 0; t < 16; t++)
                acc[t] = ffma2(*(const u64*)&X[t * 1024 + h * 64 + d0], w, acc[t]);
        }
        __syncthreads();
#pragma unroll
        for (int t = 0; t < 16; t++)
            *(u64*)&Mout[t * 1024 + g * 64 + d0] = acc[t];
    }
    __syncthreads();

    // ---- gates ----
    {
        const int t = tid >> 5, sub = tid & 31;
        const float* hrow = hidden + (size_t)(tok0 + t) * H_DIM;
        float a0 = 0.f, a1 = 0.f;
#pragma unroll 8
        for (int k = 0; k < 32; k++) {
            int j = sub + k * 32;
            float hv = hrow[j];
            float ov = Mout[t * 1024 + j];
            a0 += hv * Wg[j]        + ov * Ug[j];
            a1 += hv * Wg[1024 + j] + ov * Ug[1024 + j];
        }
#pragma unroll
        for (int off = 16; off >= 1; off >>= 1) {
            a0 += __shfl_xor_sync(0xffffffffu, a0, off);
            a1 += __shfl_xor_sync(0xffffffffu, a1, off);
        }
        if (sub == 0) {
            int s  = (tok0 + t) & (S_LEN - 1);
            int ip = pos_idx(s);
            float z0 = a0 + Vg[ip] + bg[0];
            float z1 = a1 + Vg[P_DIM + ip] + bg[1];
            gs[t * 2]     = 1.f / (1.f + expf(-z0));
            gs[t * 2 + 1] = 1.f / (1.f + expf(-z1));
        }
    }
    __syncthreads();

    // ---- final blend ----
    {
        const float4* hsrc = (const float4*)(hidden + (size_t)tok0 * H_DIM);
        float4* od = (float4*)out;
#pragma unroll
        for (int i = 0; i < 8; i++) {
            int idx = tid + i * 512;
            int t = idx >> 8;
            float g0 = gs[t * 2], g1 = gs[t * 2 + 1];
            float4 ov = ((float4*)Mout)[idx];
            float4 hv = hsrc[idx];
            od[(size_t)tok0 * 256 + idx] =
                make_float4(g0 * ov.x + g1 * hv.x, g0 * ov.y + g1 * hv.y,
                            g0 * ov.z + g1 * hv.z, g0 * ov.w + g1 * hv.w);
        }
    }
}

// ---------------------------------------------------------------------------
extern "C" void kernel_launch(void* const* d_in, const int* in_sizes, int n_in,
                              void* d_out, int out_size) {
    const float* hidden   = (const float*)d_in[0];
    const float* Wq       = (const float*)d_in[3];
    const float* Wkg      = (const float*)d_in[4];
    const float* Wkh      = (const float*)d_in[5];
    const float* Wv       = (const float*)d_in[6];
    const float* p_attn   = (const float*)d_in[7];
    const float* p_expand = (const float*)d_in[8];
    const float* Wc       = (const float*)d_in[9];
    const float* Wg       = (const float*)d_in[10];
    const float* Ug       = (const float*)d_in[11];
    const float* Vg       = (const float*)d_in[12];
    const float* bg       = (const float*)d_in[13];
    float* out = (float*)d_out;

    cudaFuncSetAttribute(k1_kernel,      cudaFuncAttributeMaxDynamicSharedMemorySize, 103424);
    cudaFuncSetAttribute(kvm_kernel,     cudaFuncAttributeMaxDynamicSharedMemorySize, 102912);
    cudaFuncSetAttribute(ctx_out_kernel, cudaFuncAttributeMaxDynamicSharedMemorySize, 225408);

    k1_kernel<<<dim3(64, 9), 256, 103424>>>(hidden, Wkg, Wq, Wv, Wc, Wkh);
    kvm_kernel<<<512, 256, 102912>>>(hidden, p_attn, p_expand);
    ctx_out_kernel<<<256, 512, 225408>>>(hidden, p_attn, p_expand,
                                         Wg, Ug, Vg, bg, out);
}

// round 14
// speedup vs baseline: 1.4103x; 1.4103x over previous
#include <cuda_runtime.h>
#include <math.h>

// ---------------------------------------------------------------------------
// LinearDescent: linear attention with per-(b,h) 64x64 state reassociation.
// B=2, S=2048, H=1024, nh=16, hd=64, kg=8, din=128, P=2112, NPF=64.
// Round 14: revert R13's kvm (atomic contention); R12 pipeline + wprep folded
// into k1 grid + mpart with 256-token blocks (4x fewer atomics, 8 contenders).
// ---------------------------------------------------------------------------

#define TOK_TOTAL 4096
#define S_LEN     2048
#define H_DIM     1024
#define NH        16
#define P_DIM     2112
#define NPF       64
#define DIN       128

typedef unsigned long long u64;
typedef unsigned int u32;

__device__ __forceinline__ u64 pack2b(float v) {
    u64 r; asm("mov.b64 %0, {%1,%1};" : "=l"(r) : "f"(v)); return r;
}
__device__ __forceinline__ u64 ffma2(u64 a, u64 b, u64 c) {
    u64 d; asm("fma.rn.f32x2 %0, %1, %2, %3;" : "=l"(d) : "l"(a), "l"(b), "l"(c)); return d;
}
__device__ __forceinline__ float2 unpk(u64 v) {
    float2 f; asm("mov.b64 {%0,%1}, %2;" : "=f"(f.x), "=f"(f.y) : "l"(v)); return f;
}
__device__ __forceinline__ void mma_tf32(float* c, u32 a0, u32 a1, u32 a2, u32 a3,
                                         u32 b0, u32 b1) {
    asm volatile("mma.sync.aligned.m16n8k8.row.col.f32.tf32.tf32.f32 "
                 "{%0,%1,%2,%3}, {%4,%5,%6,%7}, {%8,%9}, {%0,%1,%2,%3};"
                 : "+f"(c[0]), "+f"(c[1]), "+f"(c[2]), "+f"(c[3])
                 : "r"(a0), "r"(a1), "r"(a2), "r"(a3), "r"(b0), "r"(b1));
}

// scratch (device globals; allocation-free kernel_launch)
__device__ float g_k1[TOK_TOTAL * H_DIM];
__device__ float g_k [TOK_TOTAL * H_DIM];
__device__ float g_v [TOK_TOTAL * H_DIM];
__device__ float g_Mall[32 * 4096];   // per-(b,h) MT[e][d] (atomic accum)
__device__ float g_M0  [32 * 4096];   // prefix contribution (plain stores)
__device__ float g_WqT [16384];       // [g][h][d]
__device__ float g_WvT [16384];
__device__ float g_WcT [16384];
__device__ float g_WkhT[8192];        // [h8][g][dd]

__device__ __forceinline__ int pos_idx(int s) { return (s < NPF) ? (S_LEN + s) : s; }

// ---------------------------------------------------------------------------
// K1: grouped conv via tf32 mma (grid (64, 9); y==8 blocks do weight
// transposes, y<8 do the GEMM). Also zeroes g_Mall / g_M0.
// smem: Xs 64x132, Ws 128x136. 103424 B, 2 CTA/SM.
// ---------------------------------------------------------------------------
extern "C" __global__ void __launch_bounds__(256, 2)
k1_kernel(const float* __restrict__ hidden, const float* __restrict__ Wkg,
          const float* __restrict__ Wq, const float* __restrict__ Wv,
          const float* __restrict__ Wc, const float* __restrict__ Wkh) {
    extern __shared__ float sm[];
    const int tid = threadIdx.x;
    const int g   = blockIdx.y;

    if (g == 8) {                     // ---- wprep duty ----
        const int bid = blockIdx.x;
        if (bid >= 4) return;
        float* sw = sm;
        if (bid < 3) {
            const float* src = (bid == 0) ? Wq : (bid == 1) ? Wv : Wc;
            float*       dst = (bid == 0) ? g_WqT : (bid == 1) ? g_WvT : g_WcT;
            for (int i = tid; i < 4096; i += 256) ((float4*)sw)[i] = ((const float4*)src)[i];
            __syncthreads();
            for (int j = tid; j < 16384; j += 256) {
                int gg = j >> 10, rem = j & 1023, h = rem >> 6, d = rem & 63;
                dst[j] = sw[d * 256 + h * 16 + gg];
            }
        } else {
            for (int i = tid; i < 2048; i += 256) ((float4*)sw)[i] = ((const float4*)Wkh)[i];
            __syncthreads();
            for (int j = tid; j < 8192; j += 256) {
                int h8 = j >> 10, rem = j & 1023, gg = rem >> 7, dd = rem & 127;
                g_WkhT[j] = sw[dd * 64 + gg * 8 + h8];
            }
        }
        return;
    }

    float* Xs = sm;              // 64*132 = 8448
    float* Ws = sm + 8448;       // 128*136 = 17408
    const int t0 = blockIdx.x * 64;

    if (blockIdx.x < 32) {
        float4 z = make_float4(0.f, 0.f, 0.f, 0.f);
        if (g == 0) {
            float4* p = (float4*)(g_Mall + (size_t)blockIdx.x * 4096);
#pragma unroll
            for (int i = 0; i < 4; i++) p[tid + i * 256] = z;
        } else if (g == 1) {
            float4* p = (float4*)(g_M0 + (size_t)blockIdx.x * 4096);
#pragma unroll
            for (int i = 0; i < 4; i++) p[tid + i * 256] = z;
        }
    }

#pragma unroll
    for (int i = 0; i < 8; i++) {
        int j = tid + i * 256;
        int row = j >> 5, c4 = (j & 31) * 4;
        *(float4*)&Xs[row * 132 + c4] =
            *(const float4*)(hidden + (size_t)(t0 + row) * H_DIM + g * DIN + c4);
    }
#pragma unroll
    for (int i = 0; i < 16; i++) {
        int j = tid + i * 256;
        int row = j >> 5, c4 = (j & 31) * 4;
        *(float4*)&Ws[row * 136 + c4] =
            *(const float4*)(Wkg + (size_t)g * 16384 + row * 128 + c4);
    }
    __syncthreads();

    const int lane = tid & 31, wid = tid >> 5;
    const int gID = lane >> 2, tID = lane & 3;
    const int mt = wid & 3;
    const int nh = wid >> 2;
    float acc[8][4];
#pragma unroll
    for (int n = 0; n < 8; n++)
#pragma unroll
        for (int j = 0; j < 4; j++) acc[n][j] = 0.f;

    const float* Ar0 = Xs + (mt * 16 + gID) * 132;
    const float* Ar1 = Ar0 + 8 * 132;
    const float* Bbase = Ws + nh * 64 + gID;
#pragma unroll
    for (int k0 = 0; k0 < 128; k0 += 8) {
        u32 a0 = __float_as_uint(Ar0[k0 + tID]);
        u32 a1 = __float_as_uint(Ar1[k0 + tID]);
        u32 a2 = __float_as_uint(Ar0[k0 + tID + 4]);
        u32 a3 = __float_as_uint(Ar1[k0 + tID + 4]);
        const float* B0 = Bbase + (k0 + tID) * 136;
        const float* B1 = B0 + 4 * 136;
#pragma unroll
        for (int n = 0; n < 8; n++) {
            u32 b0 = __float_as_uint(B0[n * 8]);
            u32 b1 = __float_as_uint(B1[n * 8]);
            mma_tf32(acc[n], a0, a1, a2, a3, b0, b1);
        }
    }

    float* o0 = g_k1 + (size_t)(t0 + mt * 16 + gID) * H_DIM + g * DIN + nh * 64;
    float* o1 = o0 + 8 * H_DIM;
#pragma unroll
    for (int n = 0; n < 8; n++) {
        int col = n * 8 + tID * 2;
        *(float2*)&o0[col] = make_float2(acc[n][0], acc[n][1]);
        *(float2*)&o1[col] = make_float2(acc[n][2], acc[n][3]);
    }
}

// ---------------------------------------------------------------------------
// K2: k and v via d-pair ffma2 with transposed weights. 16 tok/block, 256 thr.
// ---------------------------------------------------------------------------
extern "C" __global__ void __launch_bounds__(256, 2)
kv_kernel(const float* __restrict__ hidden,
          const float* __restrict__ p_attn,
          const float* __restrict__ p_expand) {
    extern __shared__ float sm[];
    float* xs = sm;            // 16*1024
    float* ps = sm + 16384;    // 16*128
    const int tid  = threadIdx.x;
    const int tok0 = blockIdx.x * 16;

    {
        const float4* src = (const float4*)(hidden + (size_t)tok0 * H_DIM);
        float4* dst = (float4*)xs;
#pragma unroll
        for (int i = 0; i < 16; i++) dst[tid + i * 256] = src[tid + i * 256];
    }
#pragma unroll
    for (int i = 0; i < 8; i++) {
        int e = tid + i * 256;
        int t = e >> 7, c = e & 127;
        int s = (tok0 + t) & (S_LEN - 1);
        ps[e] = p_attn[(size_t)(64 + c) * P_DIM + pos_idx(s)];
    }
    __syncthreads();

    // ---- V ----
    {
        const int d0 = (tid & 31) * 2;
        const int g  = (tid >> 5) * 2;
        const u64* wv0 = (const u64*)(g_WvT + g * 1024 + d0);
        const u64* wv1 = (const u64*)(g_WvT + (g + 1) * 1024 + d0);
        const u64 pe0 = pack2b(p_expand[32 + g]);
        const u64 pe1 = pack2b(p_expand[33 + g]);
#pragma unroll
        for (int th = 0; th < 2; th++) {
            u64 acc[2][8];
#pragma unroll
            for (int t = 0; t < 8; t++) { acc[0][t] = 0ull; acc[1][t] = 0ull; }
#pragma unroll
            for (int h = 0; h < NH; h++) {
                u64 w0 = wv0[h * 32], w1 = wv1[h * 32];
#pragma unroll
                for (int t = 0; t < 8; t++) {
                    u64 x = *(const u64*)&xs[(th * 8 + t) * 1024 + h * 64 + d0];
                    acc[0][t] = ffma2(x, w0, acc[0][t]);
                    acc[1][t] = ffma2(x, w1, acc[1][t]);
                }
            }
#pragma unroll
            for (int t = 0; t < 8; t++) {
                int tt = th * 8 + t;
                u64 pv = *(const u64*)&ps[tt * 128 + 64 + d0];
                float* vb = g_v + (size_t)(tok0 + tt) * H_DIM;
                *(u64*)&vb[g * 64 + d0]       = ffma2(pe0, pv, acc[0][t]);
                *(u64*)&vb[(g + 1) * 64 + d0] = ffma2(pe1, pv, acc[1][t]);
            }
        }
    }
    // ---- K ----
    __syncthreads();
    {
        const float4* src = (const float4*)(g_k1 + (size_t)tok0 * H_DIM);
        float4* dst = (float4*)xs;
#pragma unroll
        for (int i = 0; i < 16; i++) dst[tid + i * 256] = src[tid + i * 256];
    }
    __syncthreads();
    {
        const int dd0 = (tid & 63) * 2;
        const int h8  = (tid >> 6) * 2;
        const u64* wk0 = (const u64*)(g_WkhT + h8 * 1024 + dd0);
        const u64* wk1 = (const u64*)(g_WkhT + (h8 + 1) * 1024 + dd0);
        const int jj0 = h8 * 128 + dd0;
        const int jj1 = (h8 + 1) * 128 + dd0;
        const u64 pe0 = pack2b(p_expand[16 + (jj0 >> 6)]);
        const u64 pe1 = pack2b(p_expand[16 + (jj1 >> 6)]);
        const int d64 = dd0 & 63;
#pragma unroll
        for (int th = 0; th < 2; th++) {
            u64 acc[2][8];
#pragma unroll
            for (int t = 0; t < 8; t++) { acc[0][t] = 0ull; acc[1][t] = 0ull; }
#pragma unroll
            for (int g = 0; g < 8; g++) {
                u64 w0 = wk0[g * 64], w1 = wk1[g * 64];
#pragma unroll
                for (int t = 0; t < 8; t++) {
                    u64 x = *(const u64*)&xs[(th * 8 + t) * 1024 + g * 128 + dd0];
                    acc[0][t] = ffma2(x, w0, acc[0][t]);
                    acc[1][t] = ffma2(x, w1, acc[1][t]);
                }
            }
#pragma unroll
            for (int t = 0; t < 8; t++) {
                int tt = th * 8 + t;
                u64 pk = *(const u64*)&ps[tt * 128 + d64];
                float* kb = g_k + (size_t)(tok0 + tt) * H_DIM;
                *(u64*)&kb[jj0] = ffma2(pe0, pk, acc[0][t]);
                *(u64*)&kb[jj1] = ffma2(pe1, pk, acc[1][t]);
            }
        }
    }
}

// ---------------------------------------------------------------------------
// K3: MT[e][d] += sum_t v[t,e]*k[t,d] via tf32 mma, 256 tokens (4 chunks)
// per block accumulated in registers. grid (8,16,2), 128 thr.
// Atomic contenders per address: 8. Chunk-0 block writes g_M0 plainly.
// ---------------------------------------------------------------------------
extern "C" __global__ void mpart_kernel() {
    __shared__ float vs[64 * 72];
    __shared__ float ks[64 * 72];
    const int cb = blockIdx.x;       // chunk group: chunks cb*4 .. +3
    const int h = blockIdx.y, b = blockIdx.z;
    const int tid = threadIdx.x;
    const int wid = tid >> 5, lane = tid & 31;
    const int gID = lane >> 2, tID = lane & 3;
    const int e0 = wid * 16;

    float acc[8][4];
    float m0s[8][4];
#pragma unroll
    for (int n = 0; n < 8; n++)
#pragma unroll
        for (int j = 0; j < 4; j++) acc[n][j] = 0.f;

    for (int cc = 0; cc < 4; cc++) {
        const int c = cb * 4 + cc;
        const size_t tokbase = (size_t)(b * S_LEN + c * 64);
        const float* vp = g_v + tokbase * H_DIM + h * 64;
        const float* kp = g_k + tokbase * H_DIM + h * 64;
#pragma unroll
        for (int it = 0; it < 8; it++) {
            int i = tid + it * 128;
            int row = i >> 4, c4 = (i & 15) * 4;
            *(float4*)&vs[row * 72 + c4] = *(const float4*)(vp + (size_t)row * H_DIM + c4);
            *(float4*)&ks[row * 72 + c4] = *(const float4*)(kp + (size_t)row * H_DIM + c4);
        }
        __syncthreads();

#pragma unroll
        for (int ks8 = 0; ks8 < 8; ks8++) {
            const int t0 = ks8 * 8;
            u32 a0 = __float_as_uint(vs[(t0 + tID) * 72 + e0 + gID]);
            u32 a1 = __float_as_uint(vs[(t0 + tID) * 72 + e0 + gID + 8]);
            u32 a2 = __float_as_uint(vs[(t0 + tID + 4) * 72 + e0 + gID]);
            u32 a3 = __float_as_uint(vs[(t0 + tID + 4) * 72 + e0 + gID + 8]);
#pragma unroll
            for (int n = 0; n < 8; n++) {
                u32 b0 = __float_as_uint(ks[(t0 + tID) * 72 + n * 8 + gID]);
                u32 b1 = __float_as_uint(ks[(t0 + tID + 4) * 72 + n * 8 + gID]);
                mma_tf32(acc[n], a0, a1, a2, a3, b0, b1);
            }
        }
        if (cb == 0 && cc == 0) {   // snapshot prefix contribution
#pragma unroll
            for (int n = 0; n < 8; n++)
#pragma unroll
                for (int j = 0; j < 4; j++) m0s[n][j] = acc[n][j];
        }
        __syncthreads();   // all mma reads done before next chunk overwrites
    }

    float* outp = g_Mall + (size_t)(b * 16 + h) * 4096;
    const int er0 = e0 + gID, er1 = e0 + gID + 8;
#pragma unroll
    for (int n = 0; n < 8; n++) {
        int d = n * 8 + tID * 2;
        atomicAdd(&outp[er0 * 64 + d],     acc[n][0]);
        atomicAdd(&outp[er0 * 64 + d + 1], acc[n][1]);
        atomicAdd(&outp[er1 * 64 + d],     acc[n][2]);
        atomicAdd(&outp[er1 * 64 + d + 1], acc[n][3]);
    }
    if (cb == 0) {   // sole writer per (b,h): plain stores
        float* out0 = g_M0 + (size_t)(b * 16 + h) * 4096;
#pragma unroll
        for (int n = 0; n < 8; n++) {
            int d = n * 8 + tID * 2;
            *(float2*)&out0[er0 * 64 + d] = make_float2(m0s[n][0], m0s[n][1]);
            *(float2*)&out0[er1 * 64 + d] = make_float2(m0s[n][2], m0s[n][3]);
        }
    }
}

// ---------------------------------------------------------------------------
// K4: Q proj (d-pair), ctx = q @ M via tf32 mma (4 stages x 4 heads),
// Wc (d-pair), gates, blend. 16 tok/block, 512 thr, 225.4KB, 1 CTA/SM.
// ---------------------------------------------------------------------------
extern "C" __global__ void __launch_bounds__(512, 1)
ctx_out_kernel(const float* __restrict__ hidden,
               const float* __restrict__ p_attn,
               const float* __restrict__ p_expand,
               const float* __restrict__ Wg,
               const float* __restrict__ Ug,
               const float* __restrict__ Vg,
               const float* __restrict__ bg,
               float* __restrict__ out) {
    extern __shared__ float sm[];
    float* X    = sm;
    float* qp   = sm + 16384;
    float* Mb   = sm + 35840;
    float* Mout = sm + 35840;
    float* psq  = sm + 55296;
    float* gs   = sm + 56320;
    const int tid  = threadIdx.x;
    const int tok0 = blockIdx.x * 16;
    const int b    = tok0 / S_LEN;
    const int s0   = tok0 & (S_LEN - 1);
    const bool prefix = (s0 < NPF);

    {
        const float4* src = (const float4*)(hidden + (size_t)tok0 * H_DIM);
        float4* dst = (float4*)X;
#pragma unroll
        for (int i = 0; i < 8; i++) dst[tid + i * 512] = src[tid + i * 512];
    }
#pragma unroll
    for (int i = 0; i < 2; i++) {
        int e = tid + i * 512;
        int t = e >> 6, d = e & 63;
        int s = (tok0 + t) & (S_LEN - 1);
        psq[e] = p_attn[(size_t)d * P_DIM + pos_idx(s)];
    }
    __syncthreads();

    // ---- Q -> qp (padded stride 76) ----
    {
        const int d0 = (tid & 31) * 2;
        const int g  = tid >> 5;
        const u64* wq = (const u64*)(g_WqT + g * 1024 + d0);
        u64 acc[16];
#pragma unroll
        for (int t = 0; t < 16; t++) acc[t] = 0ull;
#pragma unroll
        for (int h = 0; h < NH; h++) {
            u64 w = wq[h * 32];
#pragma unroll
            for (int t = 0; t < 16; t++)
                acc[t] = ffma2(*(const u64*)&X[t * 1024 + h * 64 + d0], w, acc[t]);
        }
        const u64 pe2 = pack2b(p_expand[g]);
        float* row = qp + g * 1216 + d0;
#pragma unroll
        for (int t = 0; t < 16; t++) {
            u64 pq = *(const u64*)&psq[t * 64 + d0];
            *(u64*)&row[t * 76] = ffma2(pe2, pq, acc[t]);
        }
    }

    // ---- ctx = q @ M via mma : 4 stages x 4 heads ----
    const int wid  = tid >> 5;
    const int lane = tid & 31;
    const int gID  = lane >> 2, tID = lane & 3;
    const int hh   = wid >> 2;
    const int nq   = wid & 3;
    const float* Ma = g_Mall + (size_t)(b * 16) * 4096;
    const float* M0 = g_M0   + (size_t)(b * 16) * 4096;

    for (int stg = 0; stg < 4; stg++) {
        __syncthreads();
        {
            const u64* msrc = (const u64*)(Ma + (size_t)stg * 16384);
            const u64* zsrc = (const u64*)(M0 + (size_t)stg * 16384);
#pragma unroll
            for (int i = 0; i < 16; i++) {
                int j = tid + i * 512;
                int h2 = j >> 11, e = (j >> 5) & 63, dp = (j & 31) * 2;
                float* dst = Mb + h2 * 4864 + e * 76 + dp;
                if (prefix) {
                    float2 A = unpk(msrc[j]), Z = unpk(zsrc[j]);
                    dst[0] = A.x - Z.x; dst[1] = A.y - Z.y;
                } else {
                    *(u64*)dst = msrc[j];
                }
            }
        }
        __syncthreads();

        const int head = stg * 4 + hh;
        const float* qb = qp + head * 1216;
        const float* mb = Mb + hh * 4864;
        float acc[2][4];
#pragma unroll
        for (int j = 0; j < 2; j++)
#pragma unroll
            for (int i = 0; i < 4; i++) acc[j][i] = 0.f;
#pragma unroll
        for (int ks8 = 0; ks8 < 8; ks8++) {
            const int k0 = ks8 * 8;
            u32 a0 = __float_as_uint(qb[gID * 76 + k0 + tID]);
            u32 a1 = __float_as_uint(qb[(gID + 8) * 76 + k0 + tID]);
            u32 a2 = __float_as_uint(qb[gID * 76 + k0 + tID + 4]);
            u32 a3 = __float_as_uint(qb[(gID + 8) * 76 + k0 + tID + 4]);
#pragma unroll
            for (int j = 0; j < 2; j++) {
                int nt = nq * 2 + j;
                u32 b0 = __float_as_uint(mb[(nt * 8 + gID) * 76 + k0 + tID]);
                u32 b1 = __float_as_uint(mb[(nt * 8 + gID) * 76 + k0 + tID + 4]);
                mma_tf32(acc[j], a0, a1, a2, a3, b0, b1);
            }
        }
#pragma unroll
        for (int j = 0; j < 2; j++) {
            int col = head * 64 + (nq * 2 + j) * 8 + 2 * tID;
            *(float2*)&X[gID * 1024 + col]       = make_float2(acc[j][0], acc[j][1]);
            *(float2*)&X[(gID + 8) * 1024 + col] = make_float2(acc[j][2], acc[j][3]);
        }
    }
    __syncthreads();

    // ---- out = Wc head-mix (d-pair) ----
    {
        const int d0 = (tid & 31) * 2;
        const int g  = tid >> 5;
        const u64* wc = (const u64*)(g_WcT + g * 1024 + d0);
        u64 acc[16];
#pragma unroll
        for (int t = 0; t < 16; t++) acc[t] = 0ull;
#pragma unroll
        for (int h = 0; h < NH; h++) {
            u64 w = wc[h * 32];
#pragma unroll
            for (int t = 0; t < 16; t++)
                acc[t] = ffma2(*(const u64*)&X[t * 1024 + h * 64 + d0], w, acc[t]);
        }
        __syncthreads();
#pragma unroll
        for (int t = 0; t < 16; t++)
            *(u64*)&Mout[t * 1024 + g * 64 + d0] = acc[t];
    }
    __syncthreads();

    // ---- gates ----
    {
        const int t = tid >> 5, sub = tid & 31;
        const float* hrow = hidden + (size_t)(tok0 + t) * H_DIM;
        float a0 = 0.f, a1 = 0.f;
#pragma unroll 8
        for (int k = 0; k < 32; k++) {
            int j = sub + k * 32;
            float hv = hrow[j];
            float ov = Mout[t * 1024 + j];
            a0 += hv * Wg[j]        + ov * Ug[j];
            a1 += hv * Wg[1024 + j] + ov * Ug[1024 + j];
        }
#pragma unroll
        for (int off = 16; off >= 1; off >>= 1) {
            a0 += __shfl_xor_sync(0xffffffffu, a0, off);
            a1 += __shfl_xor_sync(0xffffffffu, a1, off);
        }
        if (sub == 0) {
            int s  = (tok0 + t) & (S_LEN - 1);
            int ip = pos_idx(s);
            float z0 = a0 + Vg[ip] + bg[0];
            float z1 = a1 + Vg[P_DIM + ip] + bg[1];
            gs[t * 2]     = 1.f / (1.f + expf(-z0));
            gs[t * 2 + 1] = 1.f / (1.f + expf(-z1));
        }
    }
    __syncthreads();

    // ---- final blend ----
    {
        const float4* hsrc = (const float4*)(hidden + (size_t)tok0 * H_DIM);
        float4* od = (float4*)out;
#pragma unroll
        for (int i = 0; i < 8; i++) {
            int idx = tid + i * 512;
            int t = idx >> 8;
            float g0 = gs[t * 2], g1 = gs[t * 2 + 1];
            float4 ov = ((float4*)Mout)[idx];
            float4 hv = hsrc[idx];
            od[(size_t)tok0 * 256 + idx] =
                make_float4(g0 * ov.x + g1 * hv.x, g0 * ov.y + g1 * hv.y,
                            g0 * ov.z + g1 * hv.z, g0 * ov.w + g1 * hv.w);
        }
    }
}

// ---------------------------------------------------------------------------
extern "C" void kernel_launch(void* const* d_in, const int* in_sizes, int n_in,
                              void* d_out, int out_size) {
    const float* hidden   = (const float*)d_in[0];
    const float* Wq       = (const float*)d_in[3];
    const float* Wkg      = (const float*)d_in[4];
    const float* Wkh      = (const float*)d_in[5];
    const float* Wv       = (const float*)d_in[6];
    const float* p_attn   = (const float*)d_in[7];
    const float* p_expand = (const float*)d_in[8];
    const float* Wc       = (const float*)d_in[9];
    const float* Wg       = (const float*)d_in[10];
    const float* Ug       = (const float*)d_in[11];
    const float* Vg       = (const float*)d_in[12];
    const float* bg       = (const float*)d_in[13];
    float* out = (float*)d_out;

    cudaFuncSetAttribute(k1_kernel,      cudaFuncAttributeMaxDynamicSharedMemorySize, 103424);
    cudaFuncSetAttribute(kv_kernel,      cudaFuncAttributeMaxDynamicSharedMemorySize, 73728);
    cudaFuncSetAttribute(ctx_out_kernel, cudaFuncAttributeMaxDynamicSharedMemorySize, 225408);

    k1_kernel<<<dim3(64, 9), 256, 103424>>>(hidden, Wkg, Wq, Wv, Wc, Wkh);
    kv_kernel<<<256, 256, 73728>>>(hidden, p_attn, p_expand);
    mpart_kernel<<<dim3(8, 16, 2), 128>>>();
    ctx_out_kernel<<<256, 512, 225408>>>(hidden, p_attn, p_expand,
                                         Wg, Ug, Vg, bg, out);
}

// round 15
// speedup vs baseline: 1.5249x; 1.0812x over previous
#include <cuda_runtime.h>
#include <math.h>

// ---------------------------------------------------------------------------
// LinearDescent: linear attention with per-(b,h) 64x64 state reassociation.
// B=2, S=2048, H=1024, nh=16, hd=64, kg=8, din=128, P=2112, NPF=64.
// Round 15: ctx Q/Wc phases g×t register-blocked (4x less LDS traffic).
// Rest identical to R14 (109.0us).
// ---------------------------------------------------------------------------

#define TOK_TOTAL 4096
#define S_LEN     2048
#define H_DIM     1024
#define NH        16
#define P_DIM     2112
#define NPF       64
#define DIN       128

typedef unsigned long long u64;
typedef unsigned int u32;

__device__ __forceinline__ u64 pack2b(float v) {
    u64 r; asm("mov.b64 %0, {%1,%1};" : "=l"(r) : "f"(v)); return r;
}
__device__ __forceinline__ u64 ffma2(u64 a, u64 b, u64 c) {
    u64 d; asm("fma.rn.f32x2 %0, %1, %2, %3;" : "=l"(d) : "l"(a), "l"(b), "l"(c)); return d;
}
__device__ __forceinline__ float2 unpk(u64 v) {
    float2 f; asm("mov.b64 {%0,%1}, %2;" : "=f"(f.x), "=f"(f.y) : "l"(v)); return f;
}
__device__ __forceinline__ void mma_tf32(float* c, u32 a0, u32 a1, u32 a2, u32 a3,
                                         u32 b0, u32 b1) {
    asm volatile("mma.sync.aligned.m16n8k8.row.col.f32.tf32.tf32.f32 "
                 "{%0,%1,%2,%3}, {%4,%5,%6,%7}, {%8,%9}, {%0,%1,%2,%3};"
                 : "+f"(c[0]), "+f"(c[1]), "+f"(c[2]), "+f"(c[3])
                 : "r"(a0), "r"(a1), "r"(a2), "r"(a3), "r"(b0), "r"(b1));
}

// scratch (device globals; allocation-free kernel_launch)
__device__ float g_k1[TOK_TOTAL * H_DIM];
__device__ float g_k [TOK_TOTAL * H_DIM];
__device__ float g_v [TOK_TOTAL * H_DIM];
__device__ float g_Mall[32 * 4096];   // per-(b,h) MT[e][d] (atomic accum)
__device__ float g_M0  [32 * 4096];   // prefix contribution (plain stores)
__device__ float g_WqT [16384];       // [g][h][d]
__device__ float g_WvT [16384];
__device__ float g_WcT [16384];
__device__ float g_WkhT[8192];        // [h8][g][dd]

__device__ __forceinline__ int pos_idx(int s) { return (s < NPF) ? (S_LEN + s) : s; }

// ---------------------------------------------------------------------------
// K1: grouped conv via tf32 mma (grid (64, 9); y==8 blocks do weight
// transposes). Also zeroes g_Mall / g_M0.
// ---------------------------------------------------------------------------
extern "C" __global__ void __launch_bounds__(256, 2)
k1_kernel(const float* __restrict__ hidden, const float* __restrict__ Wkg,
          const float* __restrict__ Wq, const float* __restrict__ Wv,
          const float* __restrict__ Wc, const float* __restrict__ Wkh) {
    extern __shared__ float sm[];
    const int tid = threadIdx.x;
    const int g   = blockIdx.y;

    if (g == 8) {                     // ---- wprep duty ----
        const int bid = blockIdx.x;
        if (bid >= 4) return;
        float* sw = sm;
        if (bid < 3) {
            const float* src = (bid == 0) ? Wq : (bid == 1) ? Wv : Wc;
            float*       dst = (bid == 0) ? g_WqT : (bid == 1) ? g_WvT : g_WcT;
            for (int i = tid; i < 4096; i += 256) ((float4*)sw)[i] = ((const float4*)src)[i];
            __syncthreads();
            for (int j = tid; j < 16384; j += 256) {
                int gg = j >> 10, rem = j & 1023, h = rem >> 6, d = rem & 63;
                dst[j] = sw[d * 256 + h * 16 + gg];
            }
        } else {
            for (int i = tid; i < 2048; i += 256) ((float4*)sw)[i] = ((const float4*)Wkh)[i];
            __syncthreads();
            for (int j = tid; j < 8192; j += 256) {
                int h8 = j >> 10, rem = j & 1023, gg = rem >> 7, dd = rem & 127;
                g_WkhT[j] = sw[dd * 64 + gg * 8 + h8];
            }
        }
        return;
    }

    float* Xs = sm;              // 64*132
    float* Ws = sm + 8448;       // 128*136
    const int t0 = blockIdx.x * 64;

    if (blockIdx.x < 32) {
        float4 z = make_float4(0.f, 0.f, 0.f, 0.f);
        if (g == 0) {
            float4* p = (float4*)(g_Mall + (size_t)blockIdx.x * 4096);
#pragma unroll
            for (int i = 0; i < 4; i++) p[tid + i * 256] = z;
        } else if (g == 1) {
            float4* p = (float4*)(g_M0 + (size_t)blockIdx.x * 4096);
#pragma unroll
            for (int i = 0; i < 4; i++) p[tid + i * 256] = z;
        }
    }

#pragma unroll
    for (int i = 0; i < 8; i++) {
        int j = tid + i * 256;
        int row = j >> 5, c4 = (j & 31) * 4;
        *(float4*)&Xs[row * 132 + c4] =
            *(const float4*)(hidden + (size_t)(t0 + row) * H_DIM + g * DIN + c4);
    }
#pragma unroll
    for (int i = 0; i < 16; i++) {
        int j = tid + i * 256;
        int row = j >> 5, c4 = (j & 31) * 4;
        *(float4*)&Ws[row * 136 + c4] =
            *(const float4*)(Wkg + (size_t)g * 16384 + row * 128 + c4);
    }
    __syncthreads();

    const int lane = tid & 31, wid = tid >> 5;
    const int gID = lane >> 2, tID = lane & 3;
    const int mt = wid & 3;
    const int nh = wid >> 2;
    float acc[8][4];
#pragma unroll
    for (int n = 0; n < 8; n++)
#pragma unroll
        for (int j = 0; j < 4; j++) acc[n][j] = 0.f;

    const float* Ar0 = Xs + (mt * 16 + gID) * 132;
    const float* Ar1 = Ar0 + 8 * 132;
    const float* Bbase = Ws + nh * 64 + gID;
#pragma unroll
    for (int k0 = 0; k0 < 128; k0 += 8) {
        u32 a0 = __float_as_uint(Ar0[k0 + tID]);
        u32 a1 = __float_as_uint(Ar1[k0 + tID]);
        u32 a2 = __float_as_uint(Ar0[k0 + tID + 4]);
        u32 a3 = __float_as_uint(Ar1[k0 + tID + 4]);
        const float* B0 = Bbase + (k0 + tID) * 136;
        const float* B1 = B0 + 4 * 136;
#pragma unroll
        for (int n = 0; n < 8; n++) {
            u32 b0 = __float_as_uint(B0[n * 8]);
            u32 b1 = __float_as_uint(B1[n * 8]);
            mma_tf32(acc[n], a0, a1, a2, a3, b0, b1);
        }
    }

    float* o0 = g_k1 + (size_t)(t0 + mt * 16 + gID) * H_DIM + g * DIN + nh * 64;
    float* o1 = o0 + 8 * H_DIM;
#pragma unroll
    for (int n = 0; n < 8; n++) {
        int col = n * 8 + tID * 2;
        *(float2*)&o0[col] = make_float2(acc[n][0], acc[n][1]);
        *(float2*)&o1[col] = make_float2(acc[n][2], acc[n][3]);
    }
}

// ---------------------------------------------------------------------------
// K2: k and v via d-pair ffma2 with transposed weights. 16 tok/block, 256 thr.
// ---------------------------------------------------------------------------
extern "C" __global__ void __launch_bounds__(256, 2)
kv_kernel(const float* __restrict__ hidden,
          const float* __restrict__ p_attn,
          const float* __restrict__ p_expand) {
    extern __shared__ float sm[];
    float* xs = sm;            // 16*1024
    float* ps = sm + 16384;    // 16*128
    const int tid  = threadIdx.x;
    const int tok0 = blockIdx.x * 16;

    {
        const float4* src = (const float4*)(hidden + (size_t)tok0 * H_DIM);
        float4* dst = (float4*)xs;
#pragma unroll
        for (int i = 0; i < 16; i++) dst[tid + i * 256] = src[tid + i * 256];
    }
#pragma unroll
    for (int i = 0; i < 8; i++) {
        int e = tid + i * 256;
        int t = e >> 7, c = e & 127;
        int s = (tok0 + t) & (S_LEN - 1);
        ps[e] = p_attn[(size_t)(64 + c) * P_DIM + pos_idx(s)];
    }
    __syncthreads();

    // ---- V ----
    {
        const int d0 = (tid & 31) * 2;
        const int g  = (tid >> 5) * 2;
        const u64* wv0 = (const u64*)(g_WvT + g * 1024 + d0);
        const u64* wv1 = (const u64*)(g_WvT + (g + 1) * 1024 + d0);
        const u64 pe0 = pack2b(p_expand[32 + g]);
        const u64 pe1 = pack2b(p_expand[33 + g]);
#pragma unroll
        for (int th = 0; th < 2; th++) {
            u64 acc[2][8];
#pragma unroll
            for (int t = 0; t < 8; t++) { acc[0][t] = 0ull; acc[1][t] = 0ull; }
#pragma unroll
            for (int h = 0; h < NH; h++) {
                u64 w0 = wv0[h * 32], w1 = wv1[h * 32];
#pragma unroll
                for (int t = 0; t < 8; t++) {
                    u64 x = *(const u64*)&xs[(th * 8 + t) * 1024 + h * 64 + d0];
                    acc[0][t] = ffma2(x, w0, acc[0][t]);
                    acc[1][t] = ffma2(x, w1, acc[1][t]);
                }
            }
#pragma unroll
            for (int t = 0; t < 8; t++) {
                int tt = th * 8 + t;
                u64 pv = *(const u64*)&ps[tt * 128 + 64 + d0];
                float* vb = g_v + (size_t)(tok0 + tt) * H_DIM;
                *(u64*)&vb[g * 64 + d0]       = ffma2(pe0, pv, acc[0][t]);
                *(u64*)&vb[(g + 1) * 64 + d0] = ffma2(pe1, pv, acc[1][t]);
            }
        }
    }
    // ---- K ----
    __syncthreads();
    {
        const float4* src = (const float4*)(g_k1 + (size_t)tok0 * H_DIM);
        float4* dst = (float4*)xs;
#pragma unroll
        for (int i = 0; i < 16; i++) dst[tid + i * 256] = src[tid + i * 256];
    }
    __syncthreads();
    {
        const int dd0 = (tid & 63) * 2;
        const int h8  = (tid >> 6) * 2;
        const u64* wk0 = (const u64*)(g_WkhT + h8 * 1024 + dd0);
        const u64* wk1 = (const u64*)(g_WkhT + (h8 + 1) * 1024 + dd0);
        const int jj0 = h8 * 128 + dd0;
        const int jj1 = (h8 + 1) * 128 + dd0;
        const u64 pe0 = pack2b(p_expand[16 + (jj0 >> 6)]);
        const u64 pe1 = pack2b(p_expand[16 + (jj1 >> 6)]);
        const int d64 = dd0 & 63;
#pragma unroll
        for (int th = 0; th < 2; th++) {
            u64 acc[2][8];
#pragma unroll
            for (int t = 0; t < 8; t++) { acc[0][t] = 0ull; acc[1][t] = 0ull; }
#pragma unroll
            for (int g = 0; g < 8; g++) {
                u64 w0 = wk0[g * 64], w1 = wk1[g * 64];
#pragma unroll
                for (int t = 0; t < 8; t++) {
                    u64 x = *(const u64*)&xs[(th * 8 + t) * 1024 + g * 128 + dd0];
                    acc[0][t] = ffma2(x, w0, acc[0][t]);
                    acc[1][t] = ffma2(x, w1, acc[1][t]);
                }
            }
#pragma unroll
            for (int t = 0; t < 8; t++) {
                int tt = th * 8 + t;
                u64 pk = *(const u64*)&ps[tt * 128 + d64];
                float* kb = g_k + (size_t)(tok0 + tt) * H_DIM;
                *(u64*)&kb[jj0] = ffma2(pe0, pk, acc[0][t]);
                *(u64*)&kb[jj1] = ffma2(pe1, pk, acc[1][t]);
            }
        }
    }
}

// ---------------------------------------------------------------------------
// K3: MT via tf32 mma, 256 tokens (4 chunks) per block in registers.
// grid (8,16,2), 128 thr. 8 atomic contenders. Chunk-0 block writes g_M0.
// ---------------------------------------------------------------------------
extern "C" __global__ void mpart_kernel() {
    __shared__ float vs[64 * 72];
    __shared__ float ks[64 * 72];
    const int cb = blockIdx.x;
    const int h = blockIdx.y, b = blockIdx.z;
    const int tid = threadIdx.x;
    const int wid = tid >> 5, lane = tid & 31;
    const int gID = lane >> 2, tID = lane & 3;
    const int e0 = wid * 16;

    float acc[8][4];
    float m0s[8][4];
#pragma unroll
    for (int n = 0; n < 8; n++)
#pragma unroll
        for (int j = 0; j < 4; j++) acc[n][j] = 0.f;

    for (int cc = 0; cc < 4; cc++) {
        const int c = cb * 4 + cc;
        const size_t tokbase = (size_t)(b * S_LEN + c * 64);
        const float* vp = g_v + tokbase * H_DIM + h * 64;
        const float* kp = g_k + tokbase * H_DIM + h * 64;
#pragma unroll
        for (int it = 0; it < 8; it++) {
            int i = tid + it * 128;
            int row = i >> 4, c4 = (i & 15) * 4;
            *(float4*)&vs[row * 72 + c4] = *(const float4*)(vp + (size_t)row * H_DIM + c4);
            *(float4*)&ks[row * 72 + c4] = *(const float4*)(kp + (size_t)row * H_DIM + c4);
        }
        __syncthreads();

#pragma unroll
        for (int ks8 = 0; ks8 < 8; ks8++) {
            const int t0 = ks8 * 8;
            u32 a0 = __float_as_uint(vs[(t0 + tID) * 72 + e0 + gID]);
            u32 a1 = __float_as_uint(vs[(t0 + tID) * 72 + e0 + gID + 8]);
            u32 a2 = __float_as_uint(vs[(t0 + tID + 4) * 72 + e0 + gID]);
            u32 a3 = __float_as_uint(vs[(t0 + tID + 4) * 72 + e0 + gID + 8]);
#pragma unroll
            for (int n = 0; n < 8; n++) {
                u32 b0 = __float_as_uint(ks[(t0 + tID) * 72 + n * 8 + gID]);
                u32 b1 = __float_as_uint(ks[(t0 + tID + 4) * 72 + n * 8 + gID]);
                mma_tf32(acc[n], a0, a1, a2, a3, b0, b1);
            }
        }
        if (cb == 0 && cc == 0) {
#pragma unroll
            for (int n = 0; n < 8; n++)
#pragma unroll
                for (int j = 0; j < 4; j++) m0s[n][j] = acc[n][j];
        }
        __syncthreads();
    }

    float* outp = g_Mall + (size_t)(b * 16 + h) * 4096;
    const int er0 = e0 + gID, er1 = e0 + gID + 8;
#pragma unroll
    for (int n = 0; n < 8; n++) {
        int d = n * 8 + tID * 2;
        atomicAdd(&outp[er0 * 64 + d],     acc[n][0]);
        atomicAdd(&outp[er0 * 64 + d + 1], acc[n][1]);
        atomicAdd(&outp[er1 * 64 + d],     acc[n][2]);
        atomicAdd(&outp[er1 * 64 + d + 1], acc[n][3]);
    }
    if (cb == 0) {
        float* out0 = g_M0 + (size_t)(b * 16 + h) * 4096;
#pragma unroll
        for (int n = 0; n < 8; n++) {
            int d = n * 8 + tID * 2;
            *(float2*)&out0[er0 * 64 + d] = make_float2(m0s[n][0], m0s[n][1]);
            *(float2*)&out0[er1 * 64 + d] = make_float2(m0s[n][2], m0s[n][3]);
        }
    }
}

// ---------------------------------------------------------------------------
// K4: Q proj (g×t register-blocked), ctx = q @ M via tf32 mma, Wc (g×t
// blocked), gates, blend. 16 tok/block, 512 thr, 225.4KB, 1 CTA/SM.
// ---------------------------------------------------------------------------
extern "C" __global__ void __launch_bounds__(512, 1)
ctx_out_kernel(const float* __restrict__ hidden,
               const float* __restrict__ p_attn,
               const float* __restrict__ p_expand,
               const float* __restrict__ Wg,
               const float* __restrict__ Ug,
               const float* __restrict__ Vg,
               const float* __restrict__ bg,
               float* __restrict__ out) {
    extern __shared__ float sm[];
    float* X    = sm;
    float* qp   = sm + 16384;
    float* Mb   = sm + 35840;
    float* Mout = sm + 35840;
    float* psq  = sm + 55296;
    float* gs   = sm + 56320;
    const int tid  = threadIdx.x;
    const int tok0 = blockIdx.x * 16;
    const int b    = tok0 / S_LEN;
    const int s0   = tok0 & (S_LEN - 1);
    const bool prefix = (s0 < NPF);

    {
        const float4* src = (const float4*)(hidden + (size_t)tok0 * H_DIM);
        float4* dst = (float4*)X;
#pragma unroll
        for (int i = 0; i < 8; i++) dst[tid + i * 512] = src[tid + i * 512];
    }
#pragma unroll
    for (int i = 0; i < 2; i++) {
        int e = tid + i * 512;
        int t = e >> 6, d = e & 63;
        int s = (tok0 + t) & (S_LEN - 1);
        psq[e] = p_attn[(size_t)d * P_DIM + pos_idx(s)];
    }
    __syncthreads();

    const int lane = tid & 31;
    const int d0   = lane * 2;
    const int wrp  = tid >> 5;
    const int gq   = (wrp & 3) * 4;    // g-slots gq..gq+3
    const int tq   = (wrp >> 2) * 4;   // tokens tq..tq+3

    // ---- Q -> qp : 4g x 4t register tile per thread ----
    {
        u64 acc[4][4];
#pragma unroll
        for (int j = 0; j < 4; j++)
#pragma unroll
            for (int i = 0; i < 4; i++) acc[j][i] = 0ull;
        const u64* wq0 = (const u64*)(g_WqT + (gq + 0) * 1024 + d0);
        const u64* wq1 = (const u64*)(g_WqT + (gq + 1) * 1024 + d0);
        const u64* wq2 = (const u64*)(g_WqT + (gq + 2) * 1024 + d0);
        const u64* wq3 = (const u64*)(g_WqT + (gq + 3) * 1024 + d0);
#pragma unroll
        for (int h = 0; h < NH; h++) {
            u64 x0 = *(const u64*)&X[(tq + 0) * 1024 + h * 64 + d0];
            u64 x1 = *(const u64*)&X[(tq + 1) * 1024 + h * 64 + d0];
            u64 x2 = *(const u64*)&X[(tq + 2) * 1024 + h * 64 + d0];
            u64 x3 = *(const u64*)&X[(tq + 3) * 1024 + h * 64 + d0];
            u64 w0 = wq0[h * 32], w1 = wq1[h * 32], w2 = wq2[h * 32], w3 = wq3[h * 32];
            acc[0][0] = ffma2(x0, w0, acc[0][0]); acc[0][1] = ffma2(x1, w0, acc[0][1]);
            acc[0][2] = ffma2(x2, w0, acc[0][2]); acc[0][3] = ffma2(x3, w0, acc[0][3]);
            acc[1][0] = ffma2(x0, w1, acc[1][0]); acc[1][1] = ffma2(x1, w1, acc[1][1]);
            acc[1][2] = ffma2(x2, w1, acc[1][2]); acc[1][3] = ffma2(x3, w1, acc[1][3]);
            acc[2][0] = ffma2(x0, w2, acc[2][0]); acc[2][1] = ffma2(x1, w2, acc[2][1]);
            acc[2][2] = ffma2(x2, w2, acc[2][2]); acc[2][3] = ffma2(x3, w2, acc[2][3]);
            acc[3][0] = ffma2(x0, w3, acc[3][0]); acc[3][1] = ffma2(x1, w3, acc[3][1]);
            acc[3][2] = ffma2(x2, w3, acc[3][2]); acc[3][3] = ffma2(x3, w3, acc[3][3]);
        }
#pragma unroll
        for (int j = 0; j < 4; j++) {
            const u64 pe2 = pack2b(p_expand[gq + j]);
            float* row = qp + (gq + j) * 1216 + d0;
#pragma unroll
            for (int i = 0; i < 4; i++) {
                u64 pq = *(const u64*)&psq[(tq + i) * 64 + d0];
                *(u64*)&row[(tq + i) * 76] = ffma2(pe2, pq, acc[j][i]);
            }
        }
    }

    // ---- ctx = q @ M via mma : 4 stages x 4 heads ----
    const int gID  = lane >> 2, tID = lane & 3;
    const int hh   = wrp >> 2;
    const int nq   = wrp & 3;
    const float* Ma = g_Mall + (size_t)(b * 16) * 4096;
    const float* M0 = g_M0   + (size_t)(b * 16) * 4096;

    for (int stg = 0; stg < 4; stg++) {
        __syncthreads();
        {
            const u64* msrc = (const u64*)(Ma + (size_t)stg * 16384);
            const u64* zsrc = (const u64*)(M0 + (size_t)stg * 16384);
#pragma unroll
            for (int i = 0; i < 16; i++) {
                int j = tid + i * 512;
                int h2 = j >> 11, e = (j >> 5) & 63, dp = (j & 31) * 2;
                float* dst = Mb + h2 * 4864 + e * 76 + dp;
                if (prefix) {
                    float2 A = unpk(msrc[j]), Z = unpk(zsrc[j]);
                    dst[0] = A.x - Z.x; dst[1] = A.y - Z.y;
                } else {
                    *(u64*)dst = msrc[j];
                }
            }
        }
        __syncthreads();

        const int head = stg * 4 + hh;
        const float* qb = qp + head * 1216;
        const float* mb = Mb + hh * 4864;
        float acc[2][4];
#pragma unroll
        for (int j = 0; j < 2; j++)
#pragma unroll
            for (int i = 0; i < 4; i++) acc[j][i] = 0.f;
#pragma unroll
        for (int ks8 = 0; ks8 < 8; ks8++) {
            const int k0 = ks8 * 8;
            u32 a0 = __float_as_uint(qb[gID * 76 + k0 + tID]);
            u32 a1 = __float_as_uint(qb[(gID + 8) * 76 + k0 + tID]);
            u32 a2 = __float_as_uint(qb[gID * 76 + k0 + tID + 4]);
            u32 a3 = __float_as_uint(qb[(gID + 8) * 76 + k0 + tID + 4]);
#pragma unroll
            for (int j = 0; j < 2; j++) {
                int nt = nq * 2 + j;
                u32 b0 = __float_as_uint(mb[(nt * 8 + gID) * 76 + k0 + tID]);
                u32 b1 = __float_as_uint(mb[(nt * 8 + gID) * 76 + k0 + tID + 4]);
                mma_tf32(acc[j], a0, a1, a2, a3, b0, b1);
            }
        }
#pragma unroll
        for (int j = 0; j < 2; j++) {
            int col = head * 64 + (nq * 2 + j) * 8 + 2 * tID;
            *(float2*)&X[gID * 1024 + col]       = make_float2(acc[j][0], acc[j][1]);
            *(float2*)&X[(gID + 8) * 1024 + col] = make_float2(acc[j][2], acc[j][3]);
        }
    }
    __syncthreads();   // ctx complete in X; Mb free

    // ---- out = Wc head-mix : 4g x 4t register tile per thread ----
    {
        u64 acc[4][4];
#pragma unroll
        for (int j = 0; j < 4; j++)
#pragma unroll
            for (int i = 0; i < 4; i++) acc[j][i] = 0ull;
        const u64* wc0 = (const u64*)(g_WcT + (gq + 0) * 1024 + d0);
        const u64* wc1 = (const u64*)(g_WcT + (gq + 1) * 1024 + d0);
        const u64* wc2 = (const u64*)(g_WcT + (gq + 2) * 1024 + d0);
        const u64* wc3 = (const u64*)(g_WcT + (gq + 3) * 1024 + d0);
#pragma unroll
        for (int h = 0; h < NH; h++) {
            u64 x0 = *(const u64*)&X[(tq + 0) * 1024 + h * 64 + d0];
            u64 x1 = *(const u64*)&X[(tq + 1) * 1024 + h * 64 + d0];
            u64 x2 = *(const u64*)&X[(tq + 2) * 1024 + h * 64 + d0];
            u64 x3 = *(const u64*)&X[(tq + 3) * 1024 + h * 64 + d0];
            u64 w0 = wc0[h * 32], w1 = wc1[h * 32], w2 = wc2[h * 32], w3 = wc3[h * 32];
            acc[0][0] = ffma2(x0, w0, acc[0][0]); acc[0][1] = ffma2(x1, w0, acc[0][1]);
            acc[0][2] = ffma2(x2, w0, acc[0][2]); acc[0][3] = ffma2(x3, w0, acc[0][3]);
            acc[1][0] = ffma2(x0, w1, acc[1][0]); acc[1][1] = ffma2(x1, w1, acc[1][1]);
            acc[1][2] = ffma2(x2, w1, acc[1][2]); acc[1][3] = ffma2(x3, w1, acc[1][3]);
            acc[2][0] = ffma2(x0, w2, acc[2][0]); acc[2][1] = ffma2(x1, w2, acc[2][1]);
            acc[2][2] = ffma2(x2, w2, acc[2][2]); acc[2][3] = ffma2(x3, w2, acc[2][3]);
            acc[3][0] = ffma2(x0, w3, acc[3][0]); acc[3][1] = ffma2(x1, w3, acc[3][1]);
            acc[3][2] = ffma2(x2, w3, acc[3][2]); acc[3][3] = ffma2(x3, w3, acc[3][3]);
        }
#pragma unroll
        for (int j = 0; j < 4; j++)
#pragma unroll
            for (int i = 0; i < 4; i++)
                *(u64*)&Mout[(tq + i) * 1024 + (gq + j) * 64 + d0] = acc[j][i];
    }
    __syncthreads();

    // ---- gates ----
    {
        const int t = tid >> 5, sub = tid & 31;
        const float* hrow = hidden + (size_t)(tok0 + t) * H_DIM;
        float a0 = 0.f, a1 = 0.f;
#pragma unroll 8
        for (int k = 0; k < 32; k++) {
            int j = sub + k * 32;
            float hv = hrow[j];
            float ov = Mout[t * 1024 + j];
            a0 += hv * Wg[j]        + ov * Ug[j];
            a1 += hv * Wg[1024 + j] + ov * Ug[1024 + j];
        }
#pragma unroll
        for (int off = 16; off >= 1; off >>= 1) {
            a0 += __shfl_xor_sync(0xffffffffu, a0, off);
            a1 += __shfl_xor_sync(0xffffffffu, a1, off);
        }
        if (sub == 0) {
            int s  = (tok0 + t) & (S_LEN - 1);
            int ip = pos_idx(s);
            float z0 = a0 + Vg[ip] + bg[0];
            float z1 = a1 + Vg[P_DIM + ip] + bg[1];
            gs[t * 2]     = 1.f / (1.f + expf(-z0));
            gs[t * 2 + 1] = 1.f / (1.f + expf(-z1));
        }
    }
    __syncthreads();

    // ---- final blend ----
    {
        const float4* hsrc = (const float4*)(hidden + (size_t)tok0 * H_DIM);
        float4* od = (float4*)out;
#pragma unroll
        for (int i = 0; i < 8; i++) {
            int idx = tid + i * 512;
            int t = idx >> 8;
            float g0 = gs[t * 2], g1 = gs[t * 2 + 1];
            float4 ov = ((float4*)Mout)[idx];
            float4 hv = hsrc[idx];
            od[(size_t)tok0 * 256 + idx] =
                make_float4(g0 * ov.x + g1 * hv.x, g0 * ov.y + g1 * hv.y,
                            g0 * ov.z + g1 * hv.z, g0 * ov.w + g1 * hv.w);
        }
    }
}

// ---------------------------------------------------------------------------
extern "C" void kernel_launch(void* const* d_in, const int* in_sizes, int n_in,
                              void* d_out, int out_size) {
    const float* hidden   = (const float*)d_in[0];
    const float* Wq       = (const float*)d_in[3];
    const float* Wkg      = (const float*)d_in[4];
    const float* Wkh      = (const float*)d_in[5];
    const float* Wv       = (const float*)d_in[6];
    const float* p_attn   = (const float*)d_in[7];
    const float* p_expand = (const float*)d_in[8];
    const float* Wc       = (const float*)d_in[9];
    const float* Wg       = (const float*)d_in[10];
    const float* Ug       = (const float*)d_in[11];
    const float* Vg       = (const float*)d_in[12];
    const float* bg       = (const float*)d_in[13];
    float* out = (float*)d_out;

    cudaFuncSetAttribute(k1_kernel,      cudaFuncAttributeMaxDynamicSharedMemorySize, 103424);
    cudaFuncSetAttribute(kv_kernel,      cudaFuncAttributeMaxDynamicSharedMemorySize, 73728);
    cudaFuncSetAttribute(ctx_out_kernel, cudaFuncAttributeMaxDynamicSharedMemorySize, 225408);

    k1_kernel<<<dim3(64, 9), 256, 103424>>>(hidden, Wkg, Wq, Wv, Wc, Wkh);
    kv_kernel<<<256, 256, 73728>>>(hidden, p_attn, p_expand);
    mpart_kernel<<<dim3(8, 16, 2), 128>>>();
    ctx_out_kernel<<<256, 512, 225408>>>(hidden, p_attn, p_expand,
                                         Wg, Ug, Vg, bg, out);
}